// round 13
// baseline (speedup 1.0000x reference)
#include <cuda_runtime.h>
#include <cuda_bf16.h>
#include <cuda_fp16.h>
#include <math.h>
#include <stdint.h>

// B=16 T=128 S=128 V=32000 E=256 F=512 ; u=[attn;h] (1024), gates 4F=2048
__device__ float g_keys[2048 * 512];     // [b*128+s][e]
__device__ float g_Zp[128 * 2048 * 16];  // [t][c'*16+nl][b]  (c' = 0..127 col groups of 4)
__device__ float g_Wp[128 * 1024 * 16];  // [c'][k][nl]  permuted gate weights
__device__ float g_ut[2][1024 * 16];     // u transposed [k][b], parity buffered
__device__ float g_h[16 * 512];
__device__ float g_scores[16 * 128];     // [b][s]
__device__ float g_ctxT[512 * 16];       // ctx transposed [d][b]
__device__ unsigned g_barc;
__device__ unsigned g_vq;                // vocab tile queue
// fp16 operands for tensor-core vocab GEMM: A rounded, B split hi/lo
__device__ __half g_Af16[2048 * 512];
__device__ __half g_Bhi[32000 * 512];    // Wf^T : [v][k], K contiguous
__device__ __half g_Blo[32000 * 512];

__device__ __forceinline__ uint32_t smem_u32(const void* p) {
    uint32_t a;
    asm("{ .reg .u64 t; cvta.to.shared.u64 t, %1; cvt.u32.u64 %0, t; }" : "=r"(a) : "l"(p));
    return a;
}

#define LDSM4(r0, r1, r2, r3, addr) \
    asm volatile("ldmatrix.sync.aligned.m8n8.x4.shared.b16 {%0,%1,%2,%3}, [%4];" \
                 : "=r"(r0), "=r"(r1), "=r"(r2), "=r"(r3) : "r"(addr))

#define MMA16816(d, a0, a1, a2, a3, b0, b1) \
    asm volatile("mma.sync.aligned.m16n8k16.row.col.f32.f16.f16.f32 " \
                 "{%0,%1,%2,%3}, {%4,%5,%6,%7}, {%8,%9}, {%0,%1,%2,%3};" \
                 : "+f"((d)[0]), "+f"((d)[1]), "+f"((d)[2]), "+f"((d)[3]) \
                 : "r"(a0), "r"(a1), "r"(a2), "r"(a3), "r"(b0), "r"(b1))

#define CP16(sa, gp) \
    asm volatile("cp.async.cg.shared.global [%0], [%1], 16;" :: "r"(sa), "l"(gp) : "memory")

// -------- grid barrier over the 64 WORKER CTAs (4 bars per step) --------
__device__ __forceinline__ void gbar(unsigned gen) {
    __syncthreads();
    if (threadIdx.x == 0) {
        asm volatile("red.release.gpu.add.u32 [%0], 1;" :: "l"(&g_barc) : "memory");
        unsigned tgt = gen * 64u, v;
        do {
            asm volatile("ld.acquire.gpu.u32 %0, [%1];" : "=r"(v) : "l"(&g_barc) : "memory");
        } while (v < tgt);
    }
    __syncthreads();
}

__global__ void p0_init(const float* __restrict__ h0) {
    int idx = blockIdx.x * 256 + threadIdx.x;
    if (idx == 0) { g_barc = 0u; g_vq = 0u; }
    if (idx < 8192) {
        g_ut[0][idx] = 0.f;  // attn half (k<512) = 0
        int b = idx >> 9, j = idx & 511;
        g_ut[0][(512 + j) * 16 + b] = h0[idx];
    }
}

// permuted gate weights: W'[k][n], k<512 -> Wk[256+k][n] (attn rows), else Wr[k-512][n]
__global__ void p3_wperm(const float* __restrict__ Wk, const float* __restrict__ Wr) {
    int idx = blockIdx.x * 256 + threadIdx.x;  // < 2^21
    int nl = idx & 15, k = (idx >> 4) & 1023, cp = idx >> 14;
    int n = (nl >> 2) * 512 + cp * 4 + (nl & 3);
    g_Wp[idx] = (k < 512) ? Wk[(size_t)(256 + k) * 2048 + n]
                          : Wr[(size_t)(k - 512) * 2048 + n];
}

// Wf [512][32000] -> fp16 hi/lo transposed [32000][512]
__global__ void p4_bsplit(const float* __restrict__ Wf) {
    __shared__ float ts[32][33];
    int v0 = blockIdx.x * 32, k0 = blockIdx.y * 32;
    int tx = threadIdx.x, ty = threadIdx.y;
#pragma unroll
    for (int i = 0; i < 4; i++)
        ts[ty + i * 8][tx] = Wf[(size_t)(k0 + ty + i * 8) * 32000 + v0 + tx];
    __syncthreads();
#pragma unroll
    for (int i = 0; i < 4; i++) {
        int r = ty + i * 8;
        float x = ts[tx][r];
        __half hi = __float2half_rn(x);
        g_Bhi[(size_t)(v0 + r) * 512 + k0 + tx] = hi;
        g_Blo[(size_t)(v0 + r) * 512 + k0 + tx] = __float2half_rn(x - __half2float(hi));
    }
}

// 128x128x8 double-buffered fp32 SGEMM (precompute only)
// MODE0: keys=memory@Wm (N=512,K=512)  MODE1: Zp=emb[tok]@Wk[:256]+b (N=2048,K=256)
template <int MODE>
__global__ __launch_bounds__(256, 2)
void sgemm_k(const float* __restrict__ A, const float* __restrict__ Bm,
             const float* __restrict__ bias, const int* __restrict__ tokens, int K) {
    const int N = (MODE == 0) ? 512 : 2048;
    __shared__ float As[2][8][128], Bs[2][8][128];
    int tid = threadIdx.x, m0 = blockIdx.y * 128, n0 = blockIdx.x * 128;
    int lm = tid >> 1, lk = (tid & 1) * 4;
    const float* Arow;
    if (MODE == 1) {
        int m = m0 + lm;
        Arow = A + (size_t)tokens[(m & 15) * 128 + (m >> 4)] * K + lk;
    } else {
        Arow = A + (size_t)(m0 + lm) * K + lk;
    }
    int bk = tid >> 5, bn = (tid & 31) * 4;
    const float* Bptr = Bm + (size_t)bk * N + n0 + bn;

    float acc[8][8];
#pragma unroll
    for (int i = 0; i < 8; i++)
#pragma unroll
        for (int j = 0; j < 8; j++) acc[i][j] = 0.f;

    {
        float4 a4 = *(const float4*)Arow;
        float4 b4 = *(const float4*)Bptr;
        As[0][lk][lm] = a4.x; As[0][lk + 1][lm] = a4.y;
        As[0][lk + 2][lm] = a4.z; As[0][lk + 3][lm] = a4.w;
        *(float4*)&Bs[0][bk][bn] = b4;
    }
    __syncthreads();

    int nst = K / 8, buf = 0, tx = tid & 15, ty = tid >> 4;
    for (int ks = 1; ks <= nst; ks++) {
        float4 na, nb;
        if (ks < nst) {
            na = *(const float4*)(Arow + ks * 8);
            nb = *(const float4*)(Bptr + (size_t)ks * 8 * N);
        }
#pragma unroll
        for (int kk = 0; kk < 8; kk++) {
            float a[8], b[8];
            *(float4*)&a[0] = *(const float4*)&As[buf][kk][ty * 4];
            *(float4*)&a[4] = *(const float4*)&As[buf][kk][64 + ty * 4];
            *(float4*)&b[0] = *(const float4*)&Bs[buf][kk][tx * 4];
            *(float4*)&b[4] = *(const float4*)&Bs[buf][kk][64 + tx * 4];
#pragma unroll
            for (int i = 0; i < 8; i++)
#pragma unroll
                for (int j = 0; j < 8; j++) acc[i][j] += a[i] * b[j];
        }
        if (ks < nst) {
            buf ^= 1;
            As[buf][lk][lm] = na.x; As[buf][lk + 1][lm] = na.y;
            As[buf][lk + 2][lm] = na.z; As[buf][lk + 3][lm] = na.w;
            *(float4*)&Bs[buf][bk][bn] = nb;
            __syncthreads();
        }
    }

#pragma unroll
    for (int i = 0; i < 8; i++) {
        int mrow = m0 + ((i < 4) ? (ty * 4 + i) : (64 + ty * 4 + i - 4));
#pragma unroll
        for (int jh = 0; jh < 2; jh++) {
            int ncol = n0 + jh * 64 + tx * 4;
            if (MODE == 0) {
                float4 v = make_float4(acc[i][jh * 4], acc[i][jh * 4 + 1],
                                       acc[i][jh * 4 + 2], acc[i][jh * 4 + 3]);
                *(float4*)(g_keys + (size_t)mrow * 512 + ncol) = v;
            } else {
#pragma unroll
                for (int jj = 0; jj < 4; jj++) {
                    int n = ncol + jj;
                    int nl2 = (n >> 9) * 4 + (n & 3);
                    g_Zp[((size_t)(mrow >> 4) * 2048 + ((n & 511) >> 2) * 16 + nl2) * 16 +
                         (mrow & 15)] = acc[i][jh * 4 + jj] + bias[n];
                }
            }
        }
    }
}

// -------- one 128x128 vocab tile (fp16 A * fp16 hi/lo B, 3-stage cp.async) --------
__device__ __forceinline__ void vocab_tile(char* smb, uint32_t sb, int xt, int yt,
                                           const float* __restrict__ bias,
                                           float* __restrict__ out) {
    const int tid = threadIdx.x, wid = tid >> 5, lane = tid & 31;
    const int n0 = xt * 128, m0 = yt * 128;
    const int STG = 18432;                       // 3 matrices * 6144
    const int OA = 0, OBH = 6144, OBL = 12288;
    int mb = (wid >> 2) * 64, nb = (wid & 3) * 32;
    int row = tid >> 1, half = tid & 1;

    float acc[4][4][4];
#pragma unroll
    for (int i = 0; i < 4; i++)
#pragma unroll
        for (int j = 0; j < 4; j++)
#pragma unroll
            for (int q = 0; q < 4; q++) acc[i][j][q] = 0.f;

    const __half* ga = g_Af16 + (size_t)(m0 + row) * 512 + half * 8;
    const __half* gbh = g_Bhi + (size_t)(n0 + row) * 512 + half * 8;
    const __half* gbl = g_Blo + (size_t)(n0 + row) * 512 + half * 8;
    uint32_t sto = row * 48 + half * 16;

#pragma unroll
    for (int pc = 0; pc < 2; pc++) {
        uint32_t dstb = sb + pc * STG;
        CP16(dstb + OA + sto, ga + pc * 16);
        CP16(dstb + OBH + sto, gbh + pc * 16);
        CP16(dstb + OBL + sto, gbl + pc * 16);
        asm volatile("cp.async.commit_group;" ::: "memory");
    }

    uint32_t a_off = (uint32_t)((mb + (lane & 15)) * 48 + (lane >> 4) * 16);
    uint32_t b_off = (uint32_t)((nb + (lane & 7) + ((lane >> 4) & 1) * 8) * 48 +
                                ((lane >> 3) & 1) * 16);

    int stage = 0;
    for (int kc = 0; kc < 32; kc++) {
        asm volatile("cp.async.wait_group 1;" ::: "memory");
        __syncthreads();
        if (kc < 30) {
            int nstage = stage + 2;
            if (nstage >= 3) nstage -= 3;
            uint32_t dstb = sb + nstage * STG;
            CP16(dstb + OA + sto, ga + (kc + 2) * 16);
            CP16(dstb + OBH + sto, gbh + (kc + 2) * 16);
            CP16(dstb + OBL + sto, gbl + (kc + 2) * 16);
        }
        asm volatile("cp.async.commit_group;" ::: "memory");

        uint32_t sbase = sb + stage * STG;
        uint32_t aF[4][4];
#pragma unroll
        for (int mt = 0; mt < 4; mt++)
            LDSM4(aF[mt][0], aF[mt][1], aF[mt][2], aF[mt][3],
                  sbase + OA + a_off + mt * 16 * 48);
#pragma unroll
        for (int p = 0; p < 2; p++) {
            uint32_t bh0, bh1, bh2, bh3, bl0, bl1, bl2, bl3;
            LDSM4(bh0, bh1, bh2, bh3, sbase + OBH + b_off + p * 16 * 48);
            LDSM4(bl0, bl1, bl2, bl3, sbase + OBL + b_off + p * 16 * 48);
#pragma unroll
            for (int mt = 0; mt < 4; mt++) {
                MMA16816(acc[mt][p * 2], aF[mt][0], aF[mt][1], aF[mt][2], aF[mt][3],
                         bh0, bh1);
                MMA16816(acc[mt][p * 2], aF[mt][0], aF[mt][1], aF[mt][2], aF[mt][3],
                         bl0, bl1);
                MMA16816(acc[mt][p * 2 + 1], aF[mt][0], aF[mt][1], aF[mt][2], aF[mt][3],
                         bh2, bh3);
                MMA16816(acc[mt][p * 2 + 1], aF[mt][0], aF[mt][1], aF[mt][2], aF[mt][3],
                         bl2, bl3);
            }
        }
        if (++stage == 3) stage = 0;
    }
    __syncthreads();

#pragma unroll
    for (int mt = 0; mt < 4; mt++)
#pragma unroll
        for (int nt = 0; nt < 4; nt++) {
            int r0 = m0 + mb + mt * 16 + (lane >> 2);
            int col = n0 + nb + nt * 8 + (lane & 3) * 2;
            float2 bb = *(const float2*)(bias + col);
            float2 v0 = make_float2(acc[mt][nt][0] + bb.x, acc[mt][nt][1] + bb.y);
            float2 v1 = make_float2(acc[mt][nt][2] + bb.x, acc[mt][nt][3] + bb.y);
            *(float2*)(out + ((size_t)(r0 & 15) * 128 + (r0 >> 4)) * 32000 + col) = v0;
            int r1 = r0 + 8;
            *(float2*)(out + ((size_t)(r1 & 15) * 128 + (r1 >> 4)) * 32000 + col) = v1;
        }
}

// ================= fused persistent kernel: 148 CTAs, 256 threads =================
// CTAs 0..63: recurrence, 8 gate-cols each via TWO passes of the exact old 4-col code
// (pass p == old CTA c' = 2c+p  -> bitwise-identical arithmetic).
// CTAs 64..147: vocab helpers. After the loop everyone drains the tile queue.
// smem floats: sU 16384 | sPS 4096 | sZ 512 | sWa 8192 | sMem 16384  => 45568 f = 182272 B
#define O_U 0
#define O_PS 16384
#define O_Z 20480
#define O_WA 20992
#define O_MEM 29184
__global__ __launch_bounds__(256) void fused_all(const float* __restrict__ memory,
                                                 const float* __restrict__ Wa,
                                                 const float* __restrict__ c0,
                                                 const float* __restrict__ bf,
                                                 float* __restrict__ out) {
    extern __shared__ float sm[];
    const int c = blockIdx.x, tid = threadIdx.x;
    __shared__ unsigned s_tile;

    if (c < 64) {
        float* sU = sm + O_U;
        float* sPS = sm + O_PS;
        float* sZ = sm + O_Z;
        float* sWa = sm + O_WA;
        float* sMem = sm + O_MEM;
        const int ab = c >> 2;              // 4 CTAs per batch
        const int sBase = (c & 3) * 32;     // 32 scores (2 passes of 16)
        const int dBase = (c & 3) * 128;    // 128 ctx dims (2 passes of 64)

        // prologue: Wa slice [k][8] (cols (2c+p)*4+cl), memory slice [128 s][128 d]
        for (int it = 0; it < 32; it++) {
            int idx = tid + it * 256;       // < 8192
            int k = idx >> 3, col8 = idx & 7;
            int n = (2 * c + (col8 >> 2)) * 4 + (col8 & 3);
            sWa[idx] = Wa[(size_t)k * 512 + n];
        }
        for (int it = 0; it < 64; it++) {
            int idx = tid + it * 256;       // < 16384
            int s = idx >> 7, dl = idx & 127;
            sMem[idx] = memory[((size_t)ab * 128 + s) * 512 + dBase + dl];
        }
        float creg = 0.f;
        if (tid < 128) {
            int p = tid >> 6, l6 = tid & 63;
            creg = c0[(l6 >> 2) * 512 + (2 * c + p) * 4 + (l6 & 3)];
        }
        __syncthreads();

        unsigned gen = 0;
        for (int t = 0; t < 128; t++) {
            int cur = t & 1, nx = cur ^ 1;
            // ---------- phase 1: u -> smem; 2x gate GEMM (streamed weights); LSTM ----------
            const int nlr = tid >> 4, br = tid & 15;
            float zpre0 = __ldcg(g_Zp + ((size_t)t * 2048 + (2 * c) * 16 + nlr) * 16 + br);
            float zpre1 = __ldcg(g_Zp + ((size_t)t * 2048 + (2 * c + 1) * 16 + nlr) * 16 + br);
            {
                const float4* gu = (const float4*)g_ut[cur];
                float4* su4 = (float4*)sU;
#pragma unroll
                for (int i = 0; i < 16; i++) su4[tid + i * 256] = __ldcg(gu + tid + i * 256);
            }
            __syncthreads();
#pragma unroll
            for (int p = 0; p < 2; p++) {
                int nl = tid & 15, kc = tid >> 4;
                const float* wpt =
                    g_Wp + ((size_t)(2 * c + p) * 1024 + kc * 64) * 16 + nl;
                const float4* up = (const float4*)(sU + kc * 64 * 16);
                float acc[16];
#pragma unroll
                for (int i = 0; i < 16; i++) acc[i] = 0.f;
#pragma unroll 4
                for (int i = 0; i < 64; i++) {
                    float w = __ldcg(wpt + i * 16);
                    float4 u0 = up[i * 4], u1 = up[i * 4 + 1];
                    float4 u2 = up[i * 4 + 2], u3 = up[i * 4 + 3];
                    acc[0] += w * u0.x; acc[1] += w * u0.y; acc[2] += w * u0.z; acc[3] += w * u0.w;
                    acc[4] += w * u1.x; acc[5] += w * u1.y; acc[6] += w * u1.z; acc[7] += w * u1.w;
                    acc[8] += w * u2.x; acc[9] += w * u2.y; acc[10] += w * u2.z; acc[11] += w * u2.w;
                    acc[12] += w * u3.x; acc[13] += w * u3.y; acc[14] += w * u3.z; acc[15] += w * u3.w;
                }
                if (p == 1) __syncthreads();  // pass0's sPS reads done before overwrite
#pragma unroll
                for (int b = 0; b < 16; b++) sPS[(kc * 16 + nl) * 16 + b] = acc[b];
                __syncthreads();
                float z = (p == 0) ? zpre0 : zpre1;
#pragma unroll
                for (int q = 0; q < 16; q++) z += sPS[(q * 16 + nlr) * 16 + br];
                sZ[p * 256 + nlr * 16 + br] = z;
            }
            __syncthreads();
            if (tid < 128) {
                int p = tid >> 6, l6 = tid & 63, jl = l6 & 3, bb = l6 >> 2;
                const float* zb = sZ + p * 256;
                float zi = zb[jl * 16 + bb], zf = zb[(4 + jl) * 16 + bb];
                float zg = zb[(8 + jl) * 16 + bb], zo = zb[(12 + jl) * 16 + bb];
                float si = 1.f / (1.f + expf(-zi)), sf = 1.f / (1.f + expf(-zf));
                float so = 1.f / (1.f + expf(-zo));
                creg = sf * creg + si * tanhf(zg);
                float hh = so * tanhf(creg);
                int j = (2 * c + p) * 4 + jl;
                g_h[bb * 512 + j] = hh;
                g_ut[nx][(512 + j) * 16 + bb] = hh;
            }
            gbar(++gen);

            // ---------- phase 2a: scores sBase..sBase+31 (2 passes of 16; keys from L2) ----
            {
                float* h_sh = sPS;
                h_sh[tid] = __ldcg(g_h + ab * 512 + tid);
                h_sh[tid + 256] = __ldcg(g_h + ab * 512 + tid + 256);
                __syncthreads();
                if (tid < 64) {
                    int s_l = tid >> 2, q = tid & 3;
#pragma unroll
                    for (int p = 0; p < 2; p++) {
                        int s = sBase + p * 16 + s_l;
                        const float4* kp =
                            (const float4*)(g_keys + ((size_t)ab * 128 + s) * 512 + q * 128);
                        const float* hp = h_sh + q * 128;
                        float a = 0.f;
#pragma unroll 8
                        for (int i = 0; i < 32; i++) {
                            float4 kv = __ldcg(kp + i);
                            a += kv.x * hp[i * 4] + kv.y * hp[i * 4 + 1] +
                                 kv.z * hp[i * 4 + 2] + kv.w * hp[i * 4 + 3];
                        }
                        a += __shfl_xor_sync(0xffffffffu, a, 1);
                        a += __shfl_xor_sync(0xffffffffu, a, 2);
                        if (q == 0) g_scores[ab * 128 + s] = a;
                    }
                }
            }
            gbar(++gen);

            // ---------- phase 2b: softmax (exact tree) + ctx 128-d slice (2 passes) --------
            {
                float* w_sh = sPS + 512;
                float* red = sPS + 640;
                float* ctxp = sPS + 1024;   // 2 passes * 256
                if (tid < 128) w_sh[tid] = __ldcg(g_scores + ab * 128 + tid);
                __syncthreads();
                float sc = (tid < 128) ? w_sh[tid] : -1e30f;
                float mx = sc;
#pragma unroll
                for (int o = 16; o >= 1; o >>= 1)
                    mx = fmaxf(mx, __shfl_xor_sync(0xffffffffu, mx, o));
                if ((tid & 31) == 0) red[tid >> 5] = mx;
                __syncthreads();
                float gmx = fmaxf(fmaxf(red[0], red[1]), fmaxf(red[2], red[3]));
                __syncthreads();
                float e = (tid < 128) ? expf(sc - gmx) : 0.f;
                float smv = e;
#pragma unroll
                for (int o = 16; o >= 1; o >>= 1)
                    smv += __shfl_xor_sync(0xffffffffu, smv, o);
                if ((tid & 31) == 0) red[tid >> 5] = smv;
                __syncthreads();
                float gsum = red[0] + red[1] + red[2] + red[3];
                if (tid < 128) w_sh[tid] = e / gsum;
                __syncthreads();
                if (tid < 64) {
                    int sq = tid >> 4, d4l = tid & 15;
#pragma unroll
                    for (int p = 0; p < 2; p++) {
                        const float* mp = sMem + sq * 32 * 128 + p * 64;
                        float4 ca = make_float4(0.f, 0.f, 0.f, 0.f);
#pragma unroll 4
                        for (int i = 0; i < 32; i++) {
                            float w = w_sh[sq * 32 + i];
                            float4 mv = *(const float4*)(mp + i * 128 + d4l * 4);
                            ca.x += w * mv.x; ca.y += w * mv.y;
                            ca.z += w * mv.z; ca.w += w * mv.w;
                        }
                        *(float4*)&ctxp[p * 256 + sq * 64 + d4l * 4] = ca;
                    }
                }
                __syncthreads();
                if (tid < 128) {
                    int p = tid >> 6, dd = tid & 63;
                    const float* cb = ctxp + p * 256;
                    float v = cb[dd] + cb[64 + dd] + cb[128 + dd] + cb[192 + dd];
                    g_ctxT[(dBase + p * 64 + dd) * 16 + ab] = v;
                }
            }
            gbar(++gen);

            // ---------- phase 3: proj, 2 passes of the old 4-col projection ----------
            {
                const float4* hsrc = (const float4*)(g_ut[nx] + 512 * 16);
                const float4* csrc = (const float4*)g_ctxT;
                float4* du = (float4*)sU;
#pragma unroll
                for (int i = 0; i < 8; i++) du[tid + i * 256] = __ldcg(hsrc + tid + i * 256);
#pragma unroll
                for (int i = 0; i < 8; i++)
                    du[2048 + tid + i * 256] = __ldcg(csrc + tid + i * 256);
            }
            __syncthreads();
#pragma unroll
            for (int p = 0; p < 2; p++) {
                {
                    int b = tid & 15, kq = tid >> 4;
                    const float* uc = sU + kq * 64 * 16 + b;
                    const float* wbase = sWa + p * 4;
                    float a0 = 0.f, a1 = 0.f, a2 = 0.f, a3 = 0.f;
#pragma unroll 4
                    for (int i = 0; i < 64; i++) {
                        float u = uc[i * 16];
                        float4 w4 = *(const float4*)(wbase + (size_t)(kq * 64 + i) * 8);
                        a0 += u * w4.x; a1 += u * w4.y; a2 += u * w4.z; a3 += u * w4.w;
                    }
                    sPS[(kq * 4 + 0) * 16 + b] = a0;
                    sPS[(kq * 4 + 1) * 16 + b] = a1;
                    sPS[(kq * 4 + 2) * 16 + b] = a2;
                    sPS[(kq * 4 + 3) * 16 + b] = a3;
                }
                __syncthreads();
                if (tid < 64) {
                    int cl = tid >> 4, b2 = tid & 15;
                    float v = 0.f;
#pragma unroll
                    for (int q = 0; q < 16; q++) v += sPS[(q * 4 + cl) * 16 + b2];
                    int col = (2 * c + p) * 4 + cl;
                    g_ut[nx][col * 16 + b2] = v;
                    size_t row = (size_t)t * 16 + b2;
                    g_Af16[row * 512 + col] = __float2half_rn(v);
                }
                if (p == 0) __syncthreads();  // pass0's sPS reads done before pass1 writes
            }
            gbar(++gen);
        }
    }

    // ================= vocab tile queue (all 148 CTAs) =================
    char* smb = (char*)(((uintptr_t)sm + 1023) & ~(uintptr_t)1023);
    uint32_t sbv = smem_u32(smb);
    for (;;) {
        __syncthreads();
        if (tid == 0) s_tile = atomicAdd(&g_vq, 1u);
        __syncthreads();
        unsigned i = s_tile;
        if (i >= 4000u) break;
        int yt = (int)(i / 250u), xt = (int)(i - (unsigned)yt * 250u);
        if (tid == 0) {
            unsigned need = (unsigned)(yt * 8 + 8);   // steps whose attns rows tile yt reads
            unsigned tgt = 256u * need, v;            // 4 bars/step * 64 CTA arrivals
            do {
                asm volatile("ld.acquire.gpu.u32 %0, [%1];" : "=r"(v) : "l"(&g_barc)
                             : "memory");
            } while (v < tgt);
        }
        __syncthreads();
        vocab_tile(smb, sbv, xt, yt, bf, out);
    }
}

extern "C" void kernel_launch(void* const* d_in, const int* in_sizes, int n_in,
                              void* d_out, int out_size) {
    const int* tokens = (const int*)d_in[0];
    const float* memory = (const float*)d_in[1];
    const float* h0 = (const float*)d_in[2];
    const float* c0 = (const float*)d_in[3];
    const float* emb = (const float*)d_in[4];
    const float* Wk = (const float*)d_in[5];
    const float* Wr = (const float*)d_in[6];
    const float* bvec = (const float*)d_in[7];
    const float* Wm = (const float*)d_in[8];
    const float* Wa = (const float*)d_in[9];
    const float* Wf = (const float*)d_in[10];
    const float* bf = (const float*)d_in[11];
    float* out = (float*)d_out;

    cudaFuncSetAttribute(fused_all, cudaFuncAttributeMaxDynamicSharedMemorySize, 182272);

    p0_init<<<32, 256>>>(h0);
    p3_wperm<<<8192, 256>>>(Wk, Wr);
    p4_bsplit<<<dim3(1000, 16), dim3(32, 8)>>>(Wf);
    sgemm_k<0><<<dim3(4, 16), 256>>>(memory, Wm, nullptr, nullptr, 512);
    sgemm_k<1><<<dim3(16, 16), 256>>>(emb, Wk, bvec, tokens, 256);

    fused_all<<<148, 256, 182272>>>(memory, Wa, c0, bf, out);
}

// round 14
// speedup vs baseline: 1.5508x; 1.5508x over previous
#include <cuda_runtime.h>
#include <cuda_bf16.h>
#include <cuda_fp16.h>
#include <math.h>
#include <stdint.h>

// B=16 T=128 S=128 V=32000 E=256 F=512 ; u=[attn;h] (1024), gates 4F=2048
__device__ float g_keys[2048 * 512];     // [b*128+s][e]
__device__ float g_Zp[128 * 2048 * 16];  // [t][c*16+nl][b]
__device__ float g_ut[2][1024 * 16];     // u transposed [k][b], parity buffered
__device__ float g_h[16 * 512];
__device__ float g_scores[16 * 128];     // [b][s]
__device__ float g_ctxT[512 * 16];       // ctx transposed [d][b]
__device__ unsigned g_barc;
__device__ unsigned g_vq;                // vocab tile queue
// fp16 operands for tensor-core vocab GEMM (both operands rounded to fp16)
__device__ __half g_Af16[2048 * 512];
__device__ __half g_Bf16[32000 * 512];   // Wf^T : [v][k], K contiguous

__device__ __forceinline__ uint32_t smem_u32(const void* p) {
    uint32_t a;
    asm("{ .reg .u64 t; cvta.to.shared.u64 t, %1; cvt.u32.u64 %0, t; }" : "=r"(a) : "l"(p));
    return a;
}

#define LDSM4(r0, r1, r2, r3, addr) \
    asm volatile("ldmatrix.sync.aligned.m8n8.x4.shared.b16 {%0,%1,%2,%3}, [%4];" \
                 : "=r"(r0), "=r"(r1), "=r"(r2), "=r"(r3) : "r"(addr))

#define MMA16816(d, a0, a1, a2, a3, b0, b1) \
    asm volatile("mma.sync.aligned.m16n8k16.row.col.f32.f16.f16.f32 " \
                 "{%0,%1,%2,%3}, {%4,%5,%6,%7}, {%8,%9}, {%0,%1,%2,%3};" \
                 : "+f"((d)[0]), "+f"((d)[1]), "+f"((d)[2]), "+f"((d)[3]) \
                 : "r"(a0), "r"(a1), "r"(a2), "r"(a3), "r"(b0), "r"(b1))

#define CP16(sa, gp) \
    asm volatile("cp.async.cg.shared.global [%0], [%1], 16;" :: "r"(sa), "l"(gp) : "memory")

// -------- grid barrier over the 128 WORKER CTAs (4 bars per step) --------
__device__ __forceinline__ void gbar(unsigned gen) {
    __syncthreads();
    if (threadIdx.x == 0) {
        asm volatile("red.release.gpu.add.u32 [%0], 1;" :: "l"(&g_barc) : "memory");
        unsigned tgt = gen * 128u, v;
        do {
            asm volatile("ld.acquire.gpu.u32 %0, [%1];" : "=r"(v) : "l"(&g_barc) : "memory");
        } while (v < tgt);
    }
    __syncthreads();
}

__global__ void p0_init(const float* __restrict__ h0) {
    int idx = blockIdx.x * 256 + threadIdx.x;
    if (idx == 0) { g_barc = 0u; g_vq = 0u; }
    if (idx < 8192) {
        g_ut[0][idx] = 0.f;  // attn half (k<512) = 0
        int b = idx >> 9, j = idx & 511;
        g_ut[0][(512 + j) * 16 + b] = h0[idx];
    }
}

// Wf [512][32000] -> fp16 transposed [32000][512]
__global__ void p4_bsplit(const float* __restrict__ Wf) {
    __shared__ float ts[32][33];
    int v0 = blockIdx.x * 32, k0 = blockIdx.y * 32;
    int tx = threadIdx.x, ty = threadIdx.y;
#pragma unroll
    for (int i = 0; i < 4; i++)
        ts[ty + i * 8][tx] = Wf[(size_t)(k0 + ty + i * 8) * 32000 + v0 + tx];
    __syncthreads();
#pragma unroll
    for (int i = 0; i < 4; i++) {
        int r = ty + i * 8;
        g_Bf16[(size_t)(v0 + r) * 512 + k0 + tx] = __float2half_rn(ts[tx][r]);
    }
}

// 128x128x8 double-buffered fp32 SGEMM (precompute only)
// MODE0: keys=memory@Wm (N=512,K=512)  MODE1: Zp=emb[tok]@Wk[:256]+b (N=2048,K=256)
template <int MODE>
__global__ __launch_bounds__(256, 2)
void sgemm_k(const float* __restrict__ A, const float* __restrict__ Bm,
             const float* __restrict__ bias, const int* __restrict__ tokens, int K) {
    const int N = (MODE == 0) ? 512 : 2048;
    __shared__ float As[2][8][128], Bs[2][8][128];
    int tid = threadIdx.x, m0 = blockIdx.y * 128, n0 = blockIdx.x * 128;
    int lm = tid >> 1, lk = (tid & 1) * 4;
    const float* Arow;
    if (MODE == 1) {
        int m = m0 + lm;
        Arow = A + (size_t)tokens[(m & 15) * 128 + (m >> 4)] * K + lk;
    } else {
        Arow = A + (size_t)(m0 + lm) * K + lk;
    }
    int bk = tid >> 5, bn = (tid & 31) * 4;
    const float* Bptr = Bm + (size_t)bk * N + n0 + bn;

    float acc[8][8];
#pragma unroll
    for (int i = 0; i < 8; i++)
#pragma unroll
        for (int j = 0; j < 8; j++) acc[i][j] = 0.f;

    {
        float4 a4 = *(const float4*)Arow;
        float4 b4 = *(const float4*)Bptr;
        As[0][lk][lm] = a4.x; As[0][lk + 1][lm] = a4.y;
        As[0][lk + 2][lm] = a4.z; As[0][lk + 3][lm] = a4.w;
        *(float4*)&Bs[0][bk][bn] = b4;
    }
    __syncthreads();

    int nst = K / 8, buf = 0, tx = tid & 15, ty = tid >> 4;
    for (int ks = 1; ks <= nst; ks++) {
        float4 na, nb;
        if (ks < nst) {
            na = *(const float4*)(Arow + ks * 8);
            nb = *(const float4*)(Bptr + (size_t)ks * 8 * N);
        }
#pragma unroll
        for (int kk = 0; kk < 8; kk++) {
            float a[8], b[8];
            *(float4*)&a[0] = *(const float4*)&As[buf][kk][ty * 4];
            *(float4*)&a[4] = *(const float4*)&As[buf][kk][64 + ty * 4];
            *(float4*)&b[0] = *(const float4*)&Bs[buf][kk][tx * 4];
            *(float4*)&b[4] = *(const float4*)&Bs[buf][kk][64 + tx * 4];
#pragma unroll
            for (int i = 0; i < 8; i++)
#pragma unroll
                for (int j = 0; j < 8; j++) acc[i][j] += a[i] * b[j];
        }
        if (ks < nst) {
            buf ^= 1;
            As[buf][lk][lm] = na.x; As[buf][lk + 1][lm] = na.y;
            As[buf][lk + 2][lm] = na.z; As[buf][lk + 3][lm] = na.w;
            *(float4*)&Bs[buf][bk][bn] = nb;
            __syncthreads();
        }
    }

#pragma unroll
    for (int i = 0; i < 8; i++) {
        int mrow = m0 + ((i < 4) ? (ty * 4 + i) : (64 + ty * 4 + i - 4));
#pragma unroll
        for (int jh = 0; jh < 2; jh++) {
            int ncol = n0 + jh * 64 + tx * 4;
            if (MODE == 0) {
                float4 v = make_float4(acc[i][jh * 4], acc[i][jh * 4 + 1],
                                       acc[i][jh * 4 + 2], acc[i][jh * 4 + 3]);
                *(float4*)(g_keys + (size_t)mrow * 512 + ncol) = v;
            } else {
#pragma unroll
                for (int jj = 0; jj < 4; jj++) {
                    int n = ncol + jj;
                    int nl2 = (n >> 9) * 4 + (n & 3);
                    g_Zp[((size_t)(mrow >> 4) * 2048 + ((n & 511) >> 2) * 16 + nl2) * 16 +
                         (mrow & 15)] = acc[i][jh * 4 + jj] + bias[n];
                }
            }
        }
    }
}

// -------- one 128x128 vocab tile (pure fp16 HMMA, 3-stage cp.async) --------
__device__ __forceinline__ void vocab_tile(char* smb, uint32_t sb, int xt, int yt,
                                           const float* __restrict__ bias,
                                           float* __restrict__ out) {
    const int tid = threadIdx.x, wid = tid >> 5, lane = tid & 31;
    const int n0 = xt * 128, m0 = yt * 128;
    const int STG = 12288;                   // 2 matrices * 6144
    const int OA = 0, OB = 6144;
    int mb = (wid >> 2) * 64, nb = (wid & 3) * 32;
    int row = tid >> 1, half = tid & 1;

    float acc[4][4][4];
#pragma unroll
    for (int i = 0; i < 4; i++)
#pragma unroll
        for (int j = 0; j < 4; j++)
#pragma unroll
            for (int q = 0; q < 4; q++) acc[i][j][q] = 0.f;

    const __half* ga = g_Af16 + (size_t)(m0 + row) * 512 + half * 8;
    const __half* gb = g_Bf16 + (size_t)(n0 + row) * 512 + half * 8;
    uint32_t sto = row * 48 + half * 16;

#pragma unroll
    for (int pc = 0; pc < 2; pc++) {
        uint32_t dstb = sb + pc * STG;
        CP16(dstb + OA + sto, ga + pc * 16);
        CP16(dstb + OB + sto, gb + pc * 16);
        asm volatile("cp.async.commit_group;" ::: "memory");
    }

    uint32_t a_off = (uint32_t)((mb + (lane & 15)) * 48 + (lane >> 4) * 16);
    uint32_t b_off = (uint32_t)((nb + (lane & 7) + ((lane >> 4) & 1) * 8) * 48 +
                                ((lane >> 3) & 1) * 16);

    int stage = 0;
    for (int kc = 0; kc < 32; kc++) {
        asm volatile("cp.async.wait_group 1;" ::: "memory");
        __syncthreads();
        if (kc < 30) {
            int nstage = stage + 2;
            if (nstage >= 3) nstage -= 3;
            uint32_t dstb = sb + nstage * STG;
            CP16(dstb + OA + sto, ga + (kc + 2) * 16);
            CP16(dstb + OB + sto, gb + (kc + 2) * 16);
        }
        asm volatile("cp.async.commit_group;" ::: "memory");

        uint32_t sbase = sb + stage * STG;
        uint32_t aF[4][4];
#pragma unroll
        for (int mt = 0; mt < 4; mt++)
            LDSM4(aF[mt][0], aF[mt][1], aF[mt][2], aF[mt][3],
                  sbase + OA + a_off + mt * 16 * 48);
#pragma unroll
        for (int p = 0; p < 2; p++) {
            uint32_t b0, b1, b2, b3;
            LDSM4(b0, b1, b2, b3, sbase + OB + b_off + p * 16 * 48);
#pragma unroll
            for (int mt = 0; mt < 4; mt++) {
                MMA16816(acc[mt][p * 2], aF[mt][0], aF[mt][1], aF[mt][2], aF[mt][3],
                         b0, b1);
                MMA16816(acc[mt][p * 2 + 1], aF[mt][0], aF[mt][1], aF[mt][2], aF[mt][3],
                         b2, b3);
            }
        }
        if (++stage == 3) stage = 0;
    }
    __syncthreads();  // all reads of this tile's smem done before next tile reuses it

#pragma unroll
    for (int mt = 0; mt < 4; mt++)
#pragma unroll
        for (int nt = 0; nt < 4; nt++) {
            int r0 = m0 + mb + mt * 16 + (lane >> 2);
            int col = n0 + nb + nt * 8 + (lane & 3) * 2;
            float2 bb = *(const float2*)(bias + col);
            float2 v0 = make_float2(acc[mt][nt][0] + bb.x, acc[mt][nt][1] + bb.y);
            float2 v1 = make_float2(acc[mt][nt][2] + bb.x, acc[mt][nt][3] + bb.y);
            *(float2*)(out + ((size_t)(r0 & 15) * 128 + (r0 >> 4)) * 32000 + col) = v0;
            int r1 = r0 + 8;
            *(float2*)(out + ((size_t)(r1 & 15) * 128 + (r1 >> 4)) * 32000 + col) = v1;
        }
}

// ================= fused persistent kernel: 148 CTAs, 256 threads =================
// CTAs 0..127: recurrence (exact r8 arithmetic). CTAs 128..147: vocab helpers.
// After the loop, everyone drains the vocab tile queue.
#define O_WP 0
#define O_U 16384
#define O_WA 32768
#define O_PS 36864
#define O_Z 40960
#define O_KEYS 41216
#define O_MEM 49408
__global__ __launch_bounds__(256) void fused_all(const float* __restrict__ memory,
                                                 const float* __restrict__ Wk,
                                                 const float* __restrict__ Wr,
                                                 const float* __restrict__ Wa,
                                                 const float* __restrict__ c0,
                                                 const float* __restrict__ bf,
                                                 float* __restrict__ out) {
    extern __shared__ float sm[];
    const int c = blockIdx.x, tid = threadIdx.x;
    __shared__ unsigned s_tile;

    if (c < 128) {
        float* sWp = sm + O_WP;
        float* sU = sm + O_U;
        float* sWa = sm + O_WA;
        float* sPS = sm + O_PS;
        float* sZ = sm + O_Z;
        float* sKeys = sm + O_KEYS;
        float* sMem = sm + O_MEM;
        const int ab = c >> 3;
        const int s0 = (c & 7) * 16;
        const int d0 = (c & 7) * 64;

        for (int it = 0; it < 64; it++) {
            int idx = tid + it * 256;
            int k = idx >> 4, nl = idx & 15;
            int n = (nl >> 2) * 512 + c * 4 + (nl & 3);
            sWp[idx] = (k < 512) ? Wk[(size_t)(256 + k) * 2048 + n]
                                 : Wr[(size_t)(k - 512) * 2048 + n];
        }
        for (int it = 0; it < 16; it++) {
            int idx = tid + it * 256;
            sWa[idx] = Wa[(size_t)(idx >> 2) * 512 + c * 4 + (idx & 3)];
        }
        for (int i = tid; i < 8192; i += 256) {
            int r = i >> 9, k = i & 511;
            sKeys[i] = g_keys[((size_t)ab * 128 + s0 + r) * 512 + k];
        }
        for (int i = tid; i < 8192; i += 256) {
            int s = i >> 6, dl = i & 63;
            sMem[i] = memory[((size_t)ab * 128 + s) * 512 + d0 + dl];
        }
        const int jl = tid & 3, bb = tid >> 2;
        float creg = 0.f;
        if (tid < 64) creg = c0[bb * 512 + c * 4 + jl];
        __syncthreads();

        unsigned gen = 0;
        for (int t = 0; t < 128; t++) {
            int cur = t & 1, nx = cur ^ 1;
            // ---------- phase 1 ----------
            const int nlr = tid >> 4, br = tid & 15;
            float zpre = __ldcg(g_Zp + ((size_t)t * 2048 + c * 16 + nlr) * 16 + br);
            {
                const float4* gu = (const float4*)g_ut[cur];
                float4* su4 = (float4*)sU;
#pragma unroll
                for (int i = 0; i < 16; i++) su4[tid + i * 256] = __ldcg(gu + tid + i * 256);
            }
            __syncthreads();
            {
                int nl = tid & 15, kc = tid >> 4;
                const float* wp = sWp + kc * 64 * 16 + nl;
                const float4* up = (const float4*)(sU + kc * 64 * 16);
                float acc[16];
#pragma unroll
                for (int i = 0; i < 16; i++) acc[i] = 0.f;
#pragma unroll 4
                for (int i = 0; i < 64; i++) {
                    float w = wp[i * 16];
                    float4 u0 = up[i * 4], u1 = up[i * 4 + 1];
                    float4 u2 = up[i * 4 + 2], u3 = up[i * 4 + 3];
                    acc[0] += w * u0.x; acc[1] += w * u0.y; acc[2] += w * u0.z; acc[3] += w * u0.w;
                    acc[4] += w * u1.x; acc[5] += w * u1.y; acc[6] += w * u1.z; acc[7] += w * u1.w;
                    acc[8] += w * u2.x; acc[9] += w * u2.y; acc[10] += w * u2.z; acc[11] += w * u2.w;
                    acc[12] += w * u3.x; acc[13] += w * u3.y; acc[14] += w * u3.z; acc[15] += w * u3.w;
                }
#pragma unroll
                for (int b = 0; b < 16; b++) sPS[(kc * 16 + nl) * 16 + b] = acc[b];
            }
            __syncthreads();
            {
                float z = zpre;
#pragma unroll
                for (int q = 0; q < 16; q++) z += sPS[(q * 16 + nlr) * 16 + br];
                sZ[nlr * 16 + br] = z;
            }
            __syncthreads();
            if (tid < 64) {
                float zi = sZ[jl * 16 + bb], zf = sZ[(4 + jl) * 16 + bb];
                float zg = sZ[(8 + jl) * 16 + bb], zo = sZ[(12 + jl) * 16 + bb];
                float si = 1.f / (1.f + expf(-zi)), sf = 1.f / (1.f + expf(-zf));
                float so = 1.f / (1.f + expf(-zo));
                creg = sf * creg + si * tanhf(zg);
                float hh = so * tanhf(creg);
                int j = c * 4 + jl;
                g_h[bb * 512 + j] = hh;
                g_ut[nx][(512 + j) * 16 + bb] = hh;
            }
            gbar(++gen);

            // ---------- phase 2a ----------
            {
                float* h_sh = sPS;
                h_sh[tid] = __ldcg(g_h + ab * 512 + tid);
                h_sh[tid + 256] = __ldcg(g_h + ab * 512 + tid + 256);
                __syncthreads();
                if (tid < 64) {
                    int s_l = tid >> 2, q = tid & 3;
                    const float4* kp = (const float4*)(sKeys + s_l * 512 + q * 128);
                    const float* hp = h_sh + q * 128;
                    float a = 0.f;
#pragma unroll 8
                    for (int i = 0; i < 32; i++) {
                        float4 kv = kp[i];
                        a += kv.x * hp[i * 4] + kv.y * hp[i * 4 + 1] +
                             kv.z * hp[i * 4 + 2] + kv.w * hp[i * 4 + 3];
                    }
                    a += __shfl_xor_sync(0xffffffffu, a, 1);
                    a += __shfl_xor_sync(0xffffffffu, a, 2);
                    if (q == 0) g_scores[ab * 128 + s0 + s_l] = a;
                }
            }
            gbar(++gen);

            // ---------- phase 2b ----------
            {
                float* w_sh = sPS + 512;
                float* red = sPS + 640;
                float* ctxp = sPS + 1024;
                if (tid < 128) w_sh[tid] = __ldcg(g_scores + ab * 128 + tid);
                __syncthreads();
                float sc = (tid < 128) ? w_sh[tid] : -1e30f;
                float mx = sc;
#pragma unroll
                for (int o = 16; o >= 1; o >>= 1)
                    mx = fmaxf(mx, __shfl_xor_sync(0xffffffffu, mx, o));
                if ((tid & 31) == 0) red[tid >> 5] = mx;
                __syncthreads();
                float gmx = fmaxf(fmaxf(red[0], red[1]), fmaxf(red[2], red[3]));
                __syncthreads();
                float e = (tid < 128) ? expf(sc - gmx) : 0.f;
                float smv = e;
#pragma unroll
                for (int o = 16; o >= 1; o >>= 1)
                    smv += __shfl_xor_sync(0xffffffffu, smv, o);
                if ((tid & 31) == 0) red[tid >> 5] = smv;
                __syncthreads();
                float gsum = red[0] + red[1] + red[2] + red[3];
                if (tid < 128) w_sh[tid] = e / gsum;
                __syncthreads();
                if (tid < 64) {
                    int sq = tid >> 4, d4l = tid & 15;
                    const float* mp = sMem + sq * 32 * 64;
                    float4 ca = make_float4(0.f, 0.f, 0.f, 0.f);
#pragma unroll 4
                    for (int i = 0; i < 32; i++) {
                        float w = w_sh[sq * 32 + i];
                        float4 mv = *(const float4*)(mp + i * 64 + d4l * 4);
                        ca.x += w * mv.x; ca.y += w * mv.y;
                        ca.z += w * mv.z; ca.w += w * mv.w;
                    }
                    *(float4*)&ctxp[sq * 64 + d4l * 4] = ca;
                }
                __syncthreads();
                if (tid < 64) {
                    float v = ctxp[tid] + ctxp[64 + tid] + ctxp[128 + tid] + ctxp[192 + tid];
                    g_ctxT[(d0 + tid) * 16 + ab] = v;
                }
            }
            gbar(++gen);

            // ---------- phase 3 ----------
            {
                const float4* hsrc = (const float4*)(g_ut[nx] + 512 * 16);
                const float4* csrc = (const float4*)g_ctxT;
                float4* du = (float4*)sU;
#pragma unroll
                for (int i = 0; i < 8; i++) du[tid + i * 256] = __ldcg(hsrc + tid + i * 256);
#pragma unroll
                for (int i = 0; i < 8; i++)
                    du[2048 + tid + i * 256] = __ldcg(csrc + tid + i * 256);
            }
            __syncthreads();
            {
                int b = tid & 15, kq = tid >> 4;
                const float* uc = sU + kq * 64 * 16 + b;
                const float4* wv = (const float4*)(sWa + kq * 64 * 4);
                float a0 = 0.f, a1 = 0.f, a2 = 0.f, a3 = 0.f;
#pragma unroll 4
                for (int i = 0; i < 64; i++) {
                    float u = uc[i * 16];
                    float4 w4 = wv[i];
                    a0 += u * w4.x; a1 += u * w4.y; a2 += u * w4.z; a3 += u * w4.w;
                }
                sPS[(kq * 4 + 0) * 16 + b] = a0;
                sPS[(kq * 4 + 1) * 16 + b] = a1;
                sPS[(kq * 4 + 2) * 16 + b] = a2;
                sPS[(kq * 4 + 3) * 16 + b] = a3;
            }
            __syncthreads();
            if (tid < 64) {
                int cl = tid >> 4, b2 = tid & 15;
                float v = 0.f;
#pragma unroll
                for (int q = 0; q < 16; q++) v += sPS[(q * 4 + cl) * 16 + b2];
                int col = c * 4 + cl;
                g_ut[nx][col * 16 + b2] = v;
                size_t row = (size_t)t * 16 + b2;
                g_Af16[row * 512 + col] = __float2half_rn(v);
            }
            gbar(++gen);
        }
    }

    // ================= vocab tile queue (all 148 CTAs) =================
    char* smb = (char*)(((uintptr_t)sm + 1023) & ~(uintptr_t)1023);
    uint32_t sbv = smem_u32(smb);
    for (;;) {
        __syncthreads();
        if (tid == 0) s_tile = atomicAdd(&g_vq, 1u);
        __syncthreads();
        unsigned i = s_tile;
        if (i >= 4000u) break;
        int yt = (int)(i / 250u), xt = (int)(i - (unsigned)yt * 250u);
        if (tid == 0) {
            unsigned need = (unsigned)(yt * 8 + 8);   // steps whose attns rows tile yt reads
            unsigned tgt = 512u * need, v;            // 4 bars/step * 128 CTA arrivals
            do {
                asm volatile("ld.acquire.gpu.u32 %0, [%1];" : "=r"(v) : "l"(&g_barc)
                             : "memory");
            } while (v < tgt);
        }
        __syncthreads();
        vocab_tile(smb, sbv, xt, yt, bf, out);
    }
}

extern "C" void kernel_launch(void* const* d_in, const int* in_sizes, int n_in,
                              void* d_out, int out_size) {
    const int* tokens = (const int*)d_in[0];
    const float* memory = (const float*)d_in[1];
    const float* h0 = (const float*)d_in[2];
    const float* c0 = (const float*)d_in[3];
    const float* emb = (const float*)d_in[4];
    const float* Wk = (const float*)d_in[5];
    const float* Wr = (const float*)d_in[6];
    const float* bvec = (const float*)d_in[7];
    const float* Wm = (const float*)d_in[8];
    const float* Wa = (const float*)d_in[9];
    const float* Wf = (const float*)d_in[10];
    const float* bf = (const float*)d_in[11];
    float* out = (float*)d_out;

    cudaFuncSetAttribute(fused_all, cudaFuncAttributeMaxDynamicSharedMemorySize, 231424);

    p0_init<<<32, 256>>>(h0);
    p4_bsplit<<<dim3(1000, 16), dim3(32, 8)>>>(Wf);
    sgemm_k<0><<<dim3(4, 16), 256>>>(memory, Wm, nullptr, nullptr, 512);
    sgemm_k<1><<<dim3(16, 16), 256>>>(emb, Wk, bvec, tokens, 256);

    fused_all<<<148, 256, 231424>>>(memory, Wk, Wr, Wa, c0, bf, out);
}

// round 15
// speedup vs baseline: 1.5515x; 1.0004x over previous
#include <cuda_runtime.h>
#include <cuda_bf16.h>
#include <cuda_fp16.h>
#include <math.h>
#include <stdint.h>

// B=16 T=128 S=128 V=32000 E=256 F=512 ; u=[attn;h] (1024), gates 4F=2048
__device__ float g_keys[2048 * 512];     // [b*128+s][e]
__device__ float g_Zp[128 * 2048 * 16];  // [t][c*16+nl][b]
__device__ float g_ut[2][1024 * 16];     // u transposed [k][b], parity buffered
__device__ float g_h[16 * 512];
__device__ float g_scores[16 * 128];     // [b][s]
__device__ float g_ctxT[512 * 16];       // ctx transposed [d][b]
__device__ unsigned g_barc;
__device__ unsigned g_vq;                // vocab tile queue
// fp16 operands for tensor-core vocab GEMM (both operands rounded to fp16)
__device__ __half g_Af16[2048 * 512];
__device__ __half g_Bf16[32000 * 512];   // Wf^T : [v][k], K contiguous

__device__ __forceinline__ uint32_t smem_u32(const void* p) {
    uint32_t a;
    asm("{ .reg .u64 t; cvta.to.shared.u64 t, %1; cvt.u32.u64 %0, t; }" : "=r"(a) : "l"(p));
    return a;
}

#define LDSM4(r0, r1, r2, r3, addr) \
    asm volatile("ldmatrix.sync.aligned.m8n8.x4.shared.b16 {%0,%1,%2,%3}, [%4];" \
                 : "=r"(r0), "=r"(r1), "=r"(r2), "=r"(r3) : "r"(addr))

#define MMA16816(d, a0, a1, a2, a3, b0, b1) \
    asm volatile("mma.sync.aligned.m16n8k16.row.col.f32.f16.f16.f32 " \
                 "{%0,%1,%2,%3}, {%4,%5,%6,%7}, {%8,%9}, {%0,%1,%2,%3};" \
                 : "+f"((d)[0]), "+f"((d)[1]), "+f"((d)[2]), "+f"((d)[3]) \
                 : "r"(a0), "r"(a1), "r"(a2), "r"(a3), "r"(b0), "r"(b1))

#define CP16(sa, gp) \
    asm volatile("cp.async.cg.shared.global [%0], [%1], 16;" :: "r"(sa), "l"(gp) : "memory")

// -------- grid barrier over the 128 WORKER CTAs (4 bars per step) --------
__device__ __forceinline__ void gbar(unsigned gen) {
    __syncthreads();
    if (threadIdx.x == 0) {
        asm volatile("red.release.gpu.add.u32 [%0], 1;" :: "l"(&g_barc) : "memory");
        unsigned tgt = gen * 128u, v;
        do {
            asm volatile("ld.acquire.gpu.u32 %0, [%1];" : "=r"(v) : "l"(&g_barc) : "memory");
        } while (v < tgt);
    }
    __syncthreads();
}

// ================= merged precompute: p0 | keys GEMM | Zp GEMM | Wf->fp16 =================
template <int MODE>
__device__ void sgemm_body(const float* __restrict__ A, const float* __restrict__ Bm,
                           const float* __restrict__ bias, const int* __restrict__ tokens,
                           int K, int bx, int by) {
    const int N = (MODE == 0) ? 512 : 2048;
    __shared__ float As[2][8][128], Bs[2][8][128];
    int tid = threadIdx.x, m0 = by * 128, n0 = bx * 128;
    int lm = tid >> 1, lk = (tid & 1) * 4;
    const float* Arow;
    if (MODE == 1) {
        int m = m0 + lm;
        Arow = A + (size_t)tokens[(m & 15) * 128 + (m >> 4)] * K + lk;
    } else {
        Arow = A + (size_t)(m0 + lm) * K + lk;
    }
    int bk = tid >> 5, bn = (tid & 31) * 4;
    const float* Bptr = Bm + (size_t)bk * N + n0 + bn;

    float acc[8][8];
#pragma unroll
    for (int i = 0; i < 8; i++)
#pragma unroll
        for (int j = 0; j < 8; j++) acc[i][j] = 0.f;

    {
        float4 a4 = *(const float4*)Arow;
        float4 b4 = *(const float4*)Bptr;
        As[0][lk][lm] = a4.x; As[0][lk + 1][lm] = a4.y;
        As[0][lk + 2][lm] = a4.z; As[0][lk + 3][lm] = a4.w;
        *(float4*)&Bs[0][bk][bn] = b4;
    }
    __syncthreads();

    int nst = K / 8, buf = 0, tx = tid & 15, ty = tid >> 4;
    for (int ks = 1; ks <= nst; ks++) {
        float4 na, nb;
        if (ks < nst) {
            na = *(const float4*)(Arow + ks * 8);
            nb = *(const float4*)(Bptr + (size_t)ks * 8 * N);
        }
#pragma unroll
        for (int kk = 0; kk < 8; kk++) {
            float a[8], b[8];
            *(float4*)&a[0] = *(const float4*)&As[buf][kk][ty * 4];
            *(float4*)&a[4] = *(const float4*)&As[buf][kk][64 + ty * 4];
            *(float4*)&b[0] = *(const float4*)&Bs[buf][kk][tx * 4];
            *(float4*)&b[4] = *(const float4*)&Bs[buf][kk][64 + tx * 4];
#pragma unroll
            for (int i = 0; i < 8; i++)
#pragma unroll
                for (int j = 0; j < 8; j++) acc[i][j] += a[i] * b[j];
        }
        if (ks < nst) {
            buf ^= 1;
            As[buf][lk][lm] = na.x; As[buf][lk + 1][lm] = na.y;
            As[buf][lk + 2][lm] = na.z; As[buf][lk + 3][lm] = na.w;
            *(float4*)&Bs[buf][bk][bn] = nb;
            __syncthreads();
        }
    }

#pragma unroll
    for (int i = 0; i < 8; i++) {
        int mrow = m0 + ((i < 4) ? (ty * 4 + i) : (64 + ty * 4 + i - 4));
#pragma unroll
        for (int jh = 0; jh < 2; jh++) {
            int ncol = n0 + jh * 64 + tx * 4;
            if (MODE == 0) {
                float4 v = make_float4(acc[i][jh * 4], acc[i][jh * 4 + 1],
                                       acc[i][jh * 4 + 2], acc[i][jh * 4 + 3]);
                *(float4*)(g_keys + (size_t)mrow * 512 + ncol) = v;
            } else {
#pragma unroll
                for (int jj = 0; jj < 4; jj++) {
                    int n = ncol + jj;
                    int nl2 = (n >> 9) * 4 + (n & 3);
                    g_Zp[((size_t)(mrow >> 4) * 2048 + ((n & 511) >> 2) * 16 + nl2) * 16 +
                         (mrow & 15)] = acc[i][jh * 4 + jj] + bias[n];
                }
            }
        }
    }
}

__device__ void p4_body(const float* __restrict__ Wf, int q) {
    __shared__ float ts[32][33];
    int v0 = (q % 1000) * 32, k0 = (q / 1000) * 32;
    int tx = threadIdx.x & 31, ty = threadIdx.x >> 5;
#pragma unroll
    for (int i = 0; i < 4; i++)
        ts[ty + i * 8][tx] = Wf[(size_t)(k0 + ty + i * 8) * 32000 + v0 + tx];
    __syncthreads();
#pragma unroll
    for (int i = 0; i < 4; i++) {
        int r = ty + i * 8;
        g_Bf16[(size_t)(v0 + r) * 512 + k0 + tx] = __float2half_rn(ts[tx][r]);
    }
}

__global__ __launch_bounds__(256, 2) void pre_all(const float* __restrict__ h0,
                                                  const float* __restrict__ Wf,
                                                  const float* __restrict__ memory,
                                                  const float* __restrict__ Wm,
                                                  const float* __restrict__ emb,
                                                  const float* __restrict__ Wk,
                                                  const float* __restrict__ bvec,
                                                  const int* __restrict__ tokens) {
    int bid = blockIdx.x, tid = threadIdx.x;
    if (bid < 32) {
        int idx = bid * 256 + tid;
        if (idx == 0) { g_barc = 0u; g_vq = 0u; }
        if (idx < 8192) {
            g_ut[0][idx] = 0.f;
            int b = idx >> 9, j = idx & 511;
            g_ut[0][(512 + j) * 16 + b] = h0[idx];
        }
    } else if (bid < 96) {
        int q = bid - 32;
        sgemm_body<0>(memory, Wm, nullptr, nullptr, 512, q & 3, q >> 2);
    } else if (bid < 352) {
        int q = bid - 96;
        sgemm_body<1>(emb, Wk, bvec, tokens, 256, q & 15, q >> 4);
    } else {
        p4_body(Wf, bid - 352);
    }
}

// -------- one 128x128 vocab tile (pure fp16 HMMA, 6-stage cp.async, dist-5 prefetch) ------
__device__ __forceinline__ void vocab_tile(char* smb, uint32_t sb, int xt, int yt,
                                           const float* __restrict__ bias,
                                           float* __restrict__ out) {
    const int tid = threadIdx.x, wid = tid >> 5, lane = tid & 31;
    const int n0 = xt * 128, m0 = yt * 128;
    const int STG = 12288;                   // 2 matrices * 6144
    const int OA = 0, OB = 6144;
    int mb = (wid >> 2) * 64, nb = (wid & 3) * 32;
    int row = tid >> 1, half = tid & 1;

    float acc[4][4][4];
#pragma unroll
    for (int i = 0; i < 4; i++)
#pragma unroll
        for (int j = 0; j < 4; j++)
#pragma unroll
            for (int q = 0; q < 4; q++) acc[i][j][q] = 0.f;

    const __half* ga = g_Af16 + (size_t)(m0 + row) * 512 + half * 8;
    const __half* gb = g_Bf16 + (size_t)(n0 + row) * 512 + half * 8;
    uint32_t sto = row * 48 + half * 16;

    // prologue: stage chunks 0..4 into stages 0..4 (one commit each)
#pragma unroll
    for (int pc = 0; pc < 5; pc++) {
        uint32_t dstb = sb + pc * STG;
        CP16(dstb + OA + sto, ga + pc * 16);
        CP16(dstb + OB + sto, gb + pc * 16);
        asm volatile("cp.async.commit_group;" ::: "memory");
    }

    uint32_t a_off = (uint32_t)((mb + (lane & 15)) * 48 + (lane >> 4) * 16);
    uint32_t b_off = (uint32_t)((nb + (lane & 7) + ((lane >> 4) & 1) * 8) * 48 +
                                ((lane >> 3) & 1) * 16);

    int stage = 0;
    for (int kc = 0; kc < 32; kc++) {
        // chunk kc resident when all but the newest 4 groups are done
        asm volatile("cp.async.wait_group 4;" ::: "memory");
        __syncthreads();
        if (kc < 27) {
            int nstage = stage + 5;
            if (nstage >= 6) nstage -= 6;
            uint32_t dstb = sb + nstage * STG;
            CP16(dstb + OA + sto, ga + (kc + 5) * 16);
            CP16(dstb + OB + sto, gb + (kc + 5) * 16);
        }
        asm volatile("cp.async.commit_group;" ::: "memory");  // may be empty; keeps counts

        uint32_t sbase = sb + stage * STG;
        uint32_t aF[4][4];
#pragma unroll
        for (int mt = 0; mt < 4; mt++)
            LDSM4(aF[mt][0], aF[mt][1], aF[mt][2], aF[mt][3],
                  sbase + OA + a_off + mt * 16 * 48);
#pragma unroll
        for (int p = 0; p < 2; p++) {
            uint32_t b0, b1, b2, b3;
            LDSM4(b0, b1, b2, b3, sbase + OB + b_off + p * 16 * 48);
#pragma unroll
            for (int mt = 0; mt < 4; mt++) {
                MMA16816(acc[mt][p * 2], aF[mt][0], aF[mt][1], aF[mt][2], aF[mt][3],
                         b0, b1);
                MMA16816(acc[mt][p * 2 + 1], aF[mt][0], aF[mt][1], aF[mt][2], aF[mt][3],
                         b2, b3);
            }
        }
        if (++stage == 6) stage = 0;
    }
    __syncthreads();  // all reads of this tile's smem done before next tile reuses it

#pragma unroll
    for (int mt = 0; mt < 4; mt++)
#pragma unroll
        for (int nt = 0; nt < 4; nt++) {
            int r0 = m0 + mb + mt * 16 + (lane >> 2);
            int col = n0 + nb + nt * 8 + (lane & 3) * 2;
            float2 bb = *(const float2*)(bias + col);
            float2 v0 = make_float2(acc[mt][nt][0] + bb.x, acc[mt][nt][1] + bb.y);
            float2 v1 = make_float2(acc[mt][nt][2] + bb.x, acc[mt][nt][3] + bb.y);
            *(float2*)(out + ((size_t)(r0 & 15) * 128 + (r0 >> 4)) * 32000 + col) = v0;
            int r1 = r0 + 8;
            *(float2*)(out + ((size_t)(r1 & 15) * 128 + (r1 >> 4)) * 32000 + col) = v1;
        }
}

// ================= fused persistent kernel: 148 CTAs, 256 threads =================
// CTAs 0..127: recurrence (exact r8 arithmetic). CTAs 128..147: vocab helpers.
// After the loop, everyone drains the vocab tile queue.
#define O_WP 0
#define O_U 16384
#define O_WA 32768
#define O_PS 36864
#define O_Z 40960
#define O_KEYS 41216
#define O_MEM 49408
__global__ __launch_bounds__(256) void fused_all(const float* __restrict__ memory,
                                                 const float* __restrict__ Wk,
                                                 const float* __restrict__ Wr,
                                                 const float* __restrict__ Wa,
                                                 const float* __restrict__ c0,
                                                 const float* __restrict__ bf,
                                                 float* __restrict__ out) {
    extern __shared__ float sm[];
    const int c = blockIdx.x, tid = threadIdx.x;
    __shared__ unsigned s_tile;

    if (c < 128) {
        float* sWp = sm + O_WP;
        float* sU = sm + O_U;
        float* sWa = sm + O_WA;
        float* sPS = sm + O_PS;
        float* sZ = sm + O_Z;
        float* sKeys = sm + O_KEYS;
        float* sMem = sm + O_MEM;
        const int ab = c >> 3;
        const int s0 = (c & 7) * 16;
        const int d0 = (c & 7) * 64;

        for (int it = 0; it < 64; it++) {
            int idx = tid + it * 256;
            int k = idx >> 4, nl = idx & 15;
            int n = (nl >> 2) * 512 + c * 4 + (nl & 3);
            sWp[idx] = (k < 512) ? Wk[(size_t)(256 + k) * 2048 + n]
                                 : Wr[(size_t)(k - 512) * 2048 + n];
        }
        for (int it = 0; it < 16; it++) {
            int idx = tid + it * 256;
            sWa[idx] = Wa[(size_t)(idx >> 2) * 512 + c * 4 + (idx & 3)];
        }
        for (int i = tid; i < 8192; i += 256) {
            int r = i >> 9, k = i & 511;
            sKeys[i] = g_keys[((size_t)ab * 128 + s0 + r) * 512 + k];
        }
        for (int i = tid; i < 8192; i += 256) {
            int s = i >> 6, dl = i & 63;
            sMem[i] = memory[((size_t)ab * 128 + s) * 512 + d0 + dl];
        }
        const int jl = tid & 3, bb = tid >> 2;
        float creg = 0.f;
        if (tid < 64) creg = c0[bb * 512 + c * 4 + jl];
        __syncthreads();

        unsigned gen = 0;
        for (int t = 0; t < 128; t++) {
            int cur = t & 1, nx = cur ^ 1;
            // ---------- phase 1 ----------
            const int nlr = tid >> 4, br = tid & 15;
            float zpre = __ldcg(g_Zp + ((size_t)t * 2048 + c * 16 + nlr) * 16 + br);
            {
                const float4* gu = (const float4*)g_ut[cur];
                float4* su4 = (float4*)sU;
#pragma unroll
                for (int i = 0; i < 16; i++) su4[tid + i * 256] = __ldcg(gu + tid + i * 256);
            }
            __syncthreads();
            {
                int nl = tid & 15, kc = tid >> 4;
                const float* wp = sWp + kc * 64 * 16 + nl;
                const float4* up = (const float4*)(sU + kc * 64 * 16);
                float acc[16];
#pragma unroll
                for (int i = 0; i < 16; i++) acc[i] = 0.f;
#pragma unroll 4
                for (int i = 0; i < 64; i++) {
                    float w = wp[i * 16];
                    float4 u0 = up[i * 4], u1 = up[i * 4 + 1];
                    float4 u2 = up[i * 4 + 2], u3 = up[i * 4 + 3];
                    acc[0] += w * u0.x; acc[1] += w * u0.y; acc[2] += w * u0.z; acc[3] += w * u0.w;
                    acc[4] += w * u1.x; acc[5] += w * u1.y; acc[6] += w * u1.z; acc[7] += w * u1.w;
                    acc[8] += w * u2.x; acc[9] += w * u2.y; acc[10] += w * u2.z; acc[11] += w * u2.w;
                    acc[12] += w * u3.x; acc[13] += w * u3.y; acc[14] += w * u3.z; acc[15] += w * u3.w;
                }
#pragma unroll
                for (int b = 0; b < 16; b++) sPS[(kc * 16 + nl) * 16 + b] = acc[b];
            }
            __syncthreads();
            {
                float z = zpre;
#pragma unroll
                for (int q = 0; q < 16; q++) z += sPS[(q * 16 + nlr) * 16 + br];
                sZ[nlr * 16 + br] = z;
            }
            __syncthreads();
            if (tid < 64) {
                float zi = sZ[jl * 16 + bb], zf = sZ[(4 + jl) * 16 + bb];
                float zg = sZ[(8 + jl) * 16 + bb], zo = sZ[(12 + jl) * 16 + bb];
                float si = 1.f / (1.f + expf(-zi)), sf = 1.f / (1.f + expf(-zf));
                float so = 1.f / (1.f + expf(-zo));
                creg = sf * creg + si * tanhf(zg);
                float hh = so * tanhf(creg);
                int j = c * 4 + jl;
                g_h[bb * 512 + j] = hh;
                g_ut[nx][(512 + j) * 16 + bb] = hh;
            }
            gbar(++gen);

            // ---------- phase 2a ----------
            {
                float* h_sh = sPS;
                h_sh[tid] = __ldcg(g_h + ab * 512 + tid);
                h_sh[tid + 256] = __ldcg(g_h + ab * 512 + tid + 256);
                __syncthreads();
                if (tid < 64) {
                    int s_l = tid >> 2, q = tid & 3;
                    const float4* kp = (const float4*)(sKeys + s_l * 512 + q * 128);
                    const float* hp = h_sh + q * 128;
                    float a = 0.f;
#pragma unroll 8
                    for (int i = 0; i < 32; i++) {
                        float4 kv = kp[i];
                        a += kv.x * hp[i * 4] + kv.y * hp[i * 4 + 1] +
                             kv.z * hp[i * 4 + 2] + kv.w * hp[i * 4 + 3];
                    }
                    a += __shfl_xor_sync(0xffffffffu, a, 1);
                    a += __shfl_xor_sync(0xffffffffu, a, 2);
                    if (q == 0) g_scores[ab * 128 + s0 + s_l] = a;
                }
            }
            gbar(++gen);

            // ---------- phase 2b ----------
            {
                float* w_sh = sPS + 512;
                float* red = sPS + 640;
                float* ctxp = sPS + 1024;
                if (tid < 128) w_sh[tid] = __ldcg(g_scores + ab * 128 + tid);
                __syncthreads();
                float sc = (tid < 128) ? w_sh[tid] : -1e30f;
                float mx = sc;
#pragma unroll
                for (int o = 16; o >= 1; o >>= 1)
                    mx = fmaxf(mx, __shfl_xor_sync(0xffffffffu, mx, o));
                if ((tid & 31) == 0) red[tid >> 5] = mx;
                __syncthreads();
                float gmx = fmaxf(fmaxf(red[0], red[1]), fmaxf(red[2], red[3]));
                __syncthreads();
                float e = (tid < 128) ? expf(sc - gmx) : 0.f;
                float smv = e;
#pragma unroll
                for (int o = 16; o >= 1; o >>= 1)
                    smv += __shfl_xor_sync(0xffffffffu, smv, o);
                if ((tid & 31) == 0) red[tid >> 5] = smv;
                __syncthreads();
                float gsum = red[0] + red[1] + red[2] + red[3];
                if (tid < 128) w_sh[tid] = e / gsum;
                __syncthreads();
                if (tid < 64) {
                    int sq = tid >> 4, d4l = tid & 15;
                    const float* mp = sMem + sq * 32 * 64;
                    float4 ca = make_float4(0.f, 0.f, 0.f, 0.f);
#pragma unroll 4
                    for (int i = 0; i < 32; i++) {
                        float w = w_sh[sq * 32 + i];
                        float4 mv = *(const float4*)(mp + i * 64 + d4l * 4);
                        ca.x += w * mv.x; ca.y += w * mv.y;
                        ca.z += w * mv.z; ca.w += w * mv.w;
                    }
                    *(float4*)&ctxp[sq * 64 + d4l * 4] = ca;
                }
                __syncthreads();
                if (tid < 64) {
                    float v = ctxp[tid] + ctxp[64 + tid] + ctxp[128 + tid] + ctxp[192 + tid];
                    g_ctxT[(d0 + tid) * 16 + ab] = v;
                }
            }
            gbar(++gen);

            // ---------- phase 3 ----------
            {
                const float4* hsrc = (const float4*)(g_ut[nx] + 512 * 16);
                const float4* csrc = (const float4*)g_ctxT;
                float4* du = (float4*)sU;
#pragma unroll
                for (int i = 0; i < 8; i++) du[tid + i * 256] = __ldcg(hsrc + tid + i * 256);
#pragma unroll
                for (int i = 0; i < 8; i++)
                    du[2048 + tid + i * 256] = __ldcg(csrc + tid + i * 256);
            }
            __syncthreads();
            {
                int b = tid & 15, kq = tid >> 4;
                const float* uc = sU + kq * 64 * 16 + b;
                const float4* wv = (const float4*)(sWa + kq * 64 * 4);
                float a0 = 0.f, a1 = 0.f, a2 = 0.f, a3 = 0.f;
#pragma unroll 4
                for (int i = 0; i < 64; i++) {
                    float u = uc[i * 16];
                    float4 w4 = wv[i];
                    a0 += u * w4.x; a1 += u * w4.y; a2 += u * w4.z; a3 += u * w4.w;
                }
                sPS[(kq * 4 + 0) * 16 + b] = a0;
                sPS[(kq * 4 + 1) * 16 + b] = a1;
                sPS[(kq * 4 + 2) * 16 + b] = a2;
                sPS[(kq * 4 + 3) * 16 + b] = a3;
            }
            __syncthreads();
            if (tid < 64) {
                int cl = tid >> 4, b2 = tid & 15;
                float v = 0.f;
#pragma unroll
                for (int q = 0; q < 16; q++) v += sPS[(q * 4 + cl) * 16 + b2];
                int col = c * 4 + cl;
                g_ut[nx][col * 16 + b2] = v;
                size_t row = (size_t)t * 16 + b2;
                g_Af16[row * 512 + col] = __float2half_rn(v);
            }
            gbar(++gen);
        }
    }

    // ================= vocab tile queue (all 148 CTAs) =================
    char* smb = (char*)(((uintptr_t)sm + 1023) & ~(uintptr_t)1023);
    uint32_t sbv = smem_u32(smb);
    for (;;) {
        __syncthreads();
        if (tid == 0) s_tile = atomicAdd(&g_vq, 1u);
        __syncthreads();
        unsigned i = s_tile;
        if (i >= 4000u) break;
        int yt = (int)(i / 250u), xt = (int)(i - (unsigned)yt * 250u);
        if (tid == 0) {
            unsigned need = (unsigned)(yt * 8 + 8);   // steps whose attns rows tile yt reads
            unsigned tgt = 512u * need, v;            // 4 bars/step * 128 CTA arrivals
            do {
                asm volatile("ld.acquire.gpu.u32 %0, [%1];" : "=r"(v) : "l"(&g_barc)
                             : "memory");
            } while (v < tgt);
        }
        __syncthreads();
        vocab_tile(smb, sbv, xt, yt, bf, out);
    }
}

extern "C" void kernel_launch(void* const* d_in, const int* in_sizes, int n_in,
                              void* d_out, int out_size) {
    const int* tokens = (const int*)d_in[0];
    const float* memory = (const float*)d_in[1];
    const float* h0 = (const float*)d_in[2];
    const float* c0 = (const float*)d_in[3];
    const float* emb = (const float*)d_in[4];
    const float* Wk = (const float*)d_in[5];
    const float* Wr = (const float*)d_in[6];
    const float* bvec = (const float*)d_in[7];
    const float* Wm = (const float*)d_in[8];
    const float* Wa = (const float*)d_in[9];
    const float* Wf = (const float*)d_in[10];
    const float* bf = (const float*)d_in[11];
    float* out = (float*)d_out;

    cudaFuncSetAttribute(fused_all, cudaFuncAttributeMaxDynamicSharedMemorySize, 231424);

    pre_all<<<16352, 256>>>(h0, Wf, memory, Wm, emb, Wk, bvec, tokens);
    fused_all<<<148, 256, 231424>>>(memory, Wk, Wr, Wa, c0, bf, out);
}